// round 1
// baseline (speedup 1.0000x reference)
#include <cuda_runtime.h>
#include <cuda_bf16.h>

// Problem constants
#define BB 2
#define SS 2048
#define DD 1024
#define HH 16
#define HSZ 64
#define BS (BB * SS)        // 4096 rows
#define D3 (3 * DD)         // 3072
#define DFF (4 * DD)        // 4096

// ---------------- scratch (static device memory; no allocations) ----------------
__device__ float g_xn[BS * DD];        // 16 MB  (also reused as hn)
__device__ float g_wqkv[DD * D3];      // 12 MB
__device__ float g_qkv[BS * D3];       // 48 MB
__device__ float g_attn[BS * DD];      // 16 MB
__device__ float g_h[BS * DD];         // 16 MB
__device__ float g_hn[BS * DD];        // 16 MB
__device__ float g_ff[BS * DFF];       // 64 MB

// ---------------- LayerNorm: one block per row, 256 threads, 1 float4/thread ----
__global__ void ln_kernel(const float* __restrict__ in, const float* __restrict__ gamma,
                          const float* __restrict__ beta, float* __restrict__ out) {
    int row = blockIdx.x;
    int tid = threadIdx.x;
    const float4* xr = (const float4*)(in + (size_t)row * DD);
    float4 xv = xr[tid];

    __shared__ float red[256];
    float s = xv.x + xv.y + xv.z + xv.w;
    red[tid] = s;
    __syncthreads();
    #pragma unroll
    for (int off = 128; off > 0; off >>= 1) {
        if (tid < off) red[tid] += red[tid + off];
        __syncthreads();
    }
    float mu = red[0] * (1.0f / DD);
    __syncthreads();

    float dx = xv.x - mu, dy = xv.y - mu, dz = xv.z - mu, dw = xv.w - mu;
    float v = dx * dx + dy * dy + dz * dz + dw * dw;
    red[tid] = v;
    __syncthreads();
    #pragma unroll
    for (int off = 128; off > 0; off >>= 1) {
        if (tid < off) red[tid] += red[tid + off];
        __syncthreads();
    }
    float rstd = rsqrtf(red[0] * (1.0f / DD) + 1e-5f);

    float4 gv = ((const float4*)gamma)[tid];
    float4 bv = ((const float4*)beta)[tid];
    float4 ov;
    ov.x = dx * rstd * gv.x + bv.x;
    ov.y = dy * rstd * gv.y + bv.y;
    ov.z = dz * rstd * gv.z + bv.z;
    ov.w = dw * rstd * gv.w + bv.w;
    ((float4*)(out + (size_t)row * DD))[tid] = ov;
}

// ---------------- Rearrange per-head QKV weights [H,D,HS] -> [D, 3D] -----------
__global__ void build_wqkv_kernel(const float* __restrict__ wq, const float* __restrict__ wk,
                                  const float* __restrict__ wv, float* __restrict__ out) {
    int idx = blockIdx.x * 256 + threadIdx.x;
    if (idx >= DD * D3) return;
    int d = idx / D3;
    int j = idx - d * D3;
    int part = j >> 10;        // 0,1,2
    int jj = j & 1023;
    int h = jj >> 6;
    int kk = jj & 63;
    const float* w = (part == 0) ? wq : (part == 1) ? wk : wv;
    out[idx] = w[(h * DD + d) * HSZ + kk];
}

// ---------------- SGEMM: C[M,N] = A[M,K] @ B[K,N] (+bias)(+res)(relu) ----------
// 128x128 block, BK=8, 256 threads, 8x8 microtile per thread.
template <int RELU>
__global__ void sgemm_kernel(const float* __restrict__ A, const float* __restrict__ B,
                             const float* __restrict__ bias, const float* __restrict__ res,
                             float* __restrict__ C, int M, int N, int K) {
    __shared__ float As[8][128];
    __shared__ float Bs[8][128];

    int tid = threadIdx.x;
    int bx = blockIdx.x * 128;
    int by = blockIdx.y * 128;
    int tx = tid & 15;
    int ty = tid >> 4;

    int arow = tid >> 1;
    int acol = (tid & 1) << 2;
    int brow = tid >> 5;
    int bcol = (tid & 31) << 2;

    const float* Aptr = A + (size_t)(by + arow) * K + acol;
    const float* Bptr = B + (size_t)brow * N + bx + bcol;

    float acc[8][8];
    #pragma unroll
    for (int i = 0; i < 8; i++)
        #pragma unroll
        for (int j = 0; j < 8; j++) acc[i][j] = 0.0f;

    for (int k0 = 0; k0 < K; k0 += 8) {
        float4 av = *(const float4*)Aptr;
        float4 bv = *(const float4*)Bptr;
        Aptr += 8;
        Bptr += (size_t)8 * N;

        __syncthreads();
        As[acol + 0][arow] = av.x;
        As[acol + 1][arow] = av.y;
        As[acol + 2][arow] = av.z;
        As[acol + 3][arow] = av.w;
        *(float4*)&Bs[brow][bcol] = bv;
        __syncthreads();

        #pragma unroll
        for (int kk = 0; kk < 8; kk++) {
            float4 a0 = *(const float4*)&As[kk][ty * 8];
            float4 a1 = *(const float4*)&As[kk][ty * 8 + 4];
            float4 b0 = *(const float4*)&Bs[kk][tx * 8];
            float4 b1 = *(const float4*)&Bs[kk][tx * 8 + 4];
            float a[8] = {a0.x, a0.y, a0.z, a0.w, a1.x, a1.y, a1.z, a1.w};
            float bb[8] = {b0.x, b0.y, b0.z, b0.w, b1.x, b1.y, b1.z, b1.w};
            #pragma unroll
            for (int i = 0; i < 8; i++)
                #pragma unroll
                for (int j = 0; j < 8; j++)
                    acc[i][j] = fmaf(a[i], bb[j], acc[i][j]);
        }
    }

    #pragma unroll
    for (int i = 0; i < 8; i++) {
        int row = by + ty * 8 + i;
        #pragma unroll
        for (int j = 0; j < 8; j += 4) {
            int col = bx + tx * 8 + j;
            float4 v = make_float4(acc[i][j], acc[i][j + 1], acc[i][j + 2], acc[i][j + 3]);
            if (bias != nullptr) {
                float4 bv = *(const float4*)&bias[col];
                v.x += bv.x; v.y += bv.y; v.z += bv.z; v.w += bv.w;
            }
            if (res != nullptr) {
                float4 rv = *(const float4*)&res[(size_t)row * N + col];
                v.x += rv.x; v.y += rv.y; v.z += rv.z; v.w += rv.w;
            }
            if (RELU) {
                v.x = fmaxf(v.x, 0.0f); v.y = fmaxf(v.y, 0.0f);
                v.z = fmaxf(v.z, 0.0f); v.w = fmaxf(v.w, 0.0f);
            }
            *(float4*)&C[(size_t)row * N + col] = v;
        }
    }
}

// ---------------- Flash attention (causal), fp32, 64x64 tiles ------------------
// qkv layout: [BS][3072] row t = b*S + s; q at col h*64+k; k at 1024+...; v at 2048+...
// Per thread: 4 query rows (R0..R0+3) x 4 cols (C0..C0+3). 256 threads.
#define ATT_LD 68
#define ATT_SMEM_BYTES (4 * 64 * ATT_LD * 4)

__global__ void attn_kernel(const float* __restrict__ qkv, float* __restrict__ out) {
    extern __shared__ float sm[];
    float* QsT = sm;                   // [d][r]  64 x 68
    float* KsT = sm + 64 * ATT_LD;     // [d][kc]
    float* Vs  = sm + 2 * 64 * ATT_LD; // [s][c]
    float* PsT = sm + 3 * 64 * ATT_LD; // [s][r]

    int tid = threadIdx.x;
    int bh = blockIdx.y;
    int b = bh >> 4;
    int h = bh & 15;
    int q0 = blockIdx.x * 64;

    int R0 = (tid >> 4) << 2;  // 0..60
    int C0 = (tid & 15) << 2;  // 0..60

    // load Q tile transposed: thread (r = tid>>2, dg = tid&3) loads 16 floats along d
    {
        int r = tid >> 2, dg = tid & 3;
        const float* src = qkv + (size_t)(b * SS + q0 + r) * D3 + h * HSZ + dg * 16;
        #pragma unroll
        for (int i = 0; i < 4; i++) {
            float4 v = ((const float4*)src)[i];
            int d = dg * 16 + i * 4;
            QsT[(d + 0) * ATT_LD + r] = v.x;
            QsT[(d + 1) * ATT_LD + r] = v.y;
            QsT[(d + 2) * ATT_LD + r] = v.z;
            QsT[(d + 3) * ATT_LD + r] = v.w;
        }
    }

    float m[4], l[4], o[4][4];
    #pragma unroll
    for (int i = 0; i < 4; i++) {
        m[i] = -1e30f;
        l[i] = 0.0f;
        #pragma unroll
        for (int j = 0; j < 4; j++) o[i][j] = 0.0f;
    }
    const float scale = 0.125f;  // 1/sqrt(64)

    for (int k0 = 0; k0 <= q0; k0 += 64) {
        __syncthreads();  // previous iteration's PV reads done before overwriting K/V/P
        {
            int r = tid >> 2, dg = tid & 3;
            const float* ksrc = qkv + (size_t)(b * SS + k0 + r) * D3 + DD + h * HSZ + dg * 16;
            #pragma unroll
            for (int i = 0; i < 4; i++) {
                float4 v = ((const float4*)ksrc)[i];
                int d = dg * 16 + i * 4;
                KsT[(d + 0) * ATT_LD + r] = v.x;
                KsT[(d + 1) * ATT_LD + r] = v.y;
                KsT[(d + 2) * ATT_LD + r] = v.z;
                KsT[(d + 3) * ATT_LD + r] = v.w;
            }
            const float* vsrc = qkv + (size_t)(b * SS + k0 + r) * D3 + 2 * DD + h * HSZ + dg * 16;
            #pragma unroll
            for (int i = 0; i < 4; i++) {
                ((float4*)&Vs[r * ATT_LD + dg * 16])[i] = ((const float4*)vsrc)[i];
            }
        }
        __syncthreads();

        // S = Q K^T : 4x4 fragment
        float s4[4][4];
        #pragma unroll
        for (int i = 0; i < 4; i++)
            #pragma unroll
            for (int j = 0; j < 4; j++) s4[i][j] = 0.0f;

        #pragma unroll
        for (int d = 0; d < 64; d++) {
            float4 qa = *(const float4*)&QsT[d * ATT_LD + R0];
            float4 kb = *(const float4*)&KsT[d * ATT_LD + C0];
            float a[4] = {qa.x, qa.y, qa.z, qa.w};
            float bb[4] = {kb.x, kb.y, kb.z, kb.w};
            #pragma unroll
            for (int i = 0; i < 4; i++)
                #pragma unroll
                for (int j = 0; j < 4; j++)
                    s4[i][j] = fmaf(a[i], bb[j], s4[i][j]);
        }

        bool diag = (k0 == q0);
        #pragma unroll
        for (int i = 0; i < 4; i++)
            #pragma unroll
            for (int j = 0; j < 4; j++) {
                s4[i][j] *= scale;
                if (diag && (C0 + j > R0 + i)) s4[i][j] = -1e30f;
            }

        // online softmax update
        #pragma unroll
        for (int i = 0; i < 4; i++) {
            float tm = fmaxf(fmaxf(s4[i][0], s4[i][1]), fmaxf(s4[i][2], s4[i][3]));
            tm = fmaxf(tm, __shfl_xor_sync(0xffffffffu, tm, 1));
            tm = fmaxf(tm, __shfl_xor_sync(0xffffffffu, tm, 2));
            tm = fmaxf(tm, __shfl_xor_sync(0xffffffffu, tm, 4));
            tm = fmaxf(tm, __shfl_xor_sync(0xffffffffu, tm, 8));
            float mn = fmaxf(m[i], tm);
            float alpha = __expf(m[i] - mn);
            m[i] = mn;
            float ls = 0.0f;
            #pragma unroll
            for (int j = 0; j < 4; j++) {
                s4[i][j] = __expf(s4[i][j] - mn);
                ls += s4[i][j];
            }
            ls += __shfl_xor_sync(0xffffffffu, ls, 1);
            ls += __shfl_xor_sync(0xffffffffu, ls, 2);
            ls += __shfl_xor_sync(0xffffffffu, ls, 4);
            ls += __shfl_xor_sync(0xffffffffu, ls, 8);
            l[i] = l[i] * alpha + ls;
            #pragma unroll
            for (int j = 0; j < 4; j++) o[i][j] *= alpha;
        }

        // store P transposed: PsT[key s][query r]
        #pragma unroll
        for (int j = 0; j < 4; j++) {
            float4 pv = make_float4(s4[0][j], s4[1][j], s4[2][j], s4[3][j]);
            *(float4*)&PsT[(C0 + j) * ATT_LD + R0] = pv;
        }
        __syncthreads();

        // O += P @ V
        #pragma unroll
        for (int s = 0; s < 64; s++) {
            float4 pa = *(const float4*)&PsT[s * ATT_LD + R0];
            float4 vb = *(const float4*)&Vs[s * ATT_LD + C0];
            float p[4] = {pa.x, pa.y, pa.z, pa.w};
            float v[4] = {vb.x, vb.y, vb.z, vb.w};
            #pragma unroll
            for (int i = 0; i < 4; i++)
                #pragma unroll
                for (int j = 0; j < 4; j++)
                    o[i][j] = fmaf(p[i], v[j], o[i][j]);
        }
    }

    // epilogue: normalize and write concat-head layout [B,S,D]
    #pragma unroll
    for (int i = 0; i < 4; i++) {
        int row = q0 + R0 + i;
        float inv = 1.0f / l[i];
        float4 ov = make_float4(o[i][0] * inv, o[i][1] * inv, o[i][2] * inv, o[i][3] * inv);
        *(float4*)&out[(size_t)(b * SS + row) * DD + h * HSZ + C0] = ov;
    }
}

// ---------------- launch ----------------
extern "C" void kernel_launch(void* const* d_in, const int* in_sizes, int n_in,
                              void* d_out, int out_size) {
    const float* x     = (const float*)d_in[0];
    const float* wq    = (const float*)d_in[1];
    const float* wk    = (const float*)d_in[2];
    const float* wv    = (const float*)d_in[3];
    const float* wproj = (const float*)d_in[4];
    const float* bproj = (const float*)d_in[5];
    const float* w1    = (const float*)d_in[6];
    const float* b1    = (const float*)d_in[7];
    const float* w2    = (const float*)d_in[8];
    const float* b2    = (const float*)d_in[9];
    const float* ln1_g = (const float*)d_in[10];
    const float* ln1_b = (const float*)d_in[11];
    const float* ln2_g = (const float*)d_in[12];
    const float* ln2_b = (const float*)d_in[13];
    float* out = (float*)d_out;

    float *p_xn, *p_wqkv, *p_qkv, *p_attn, *p_h, *p_hn, *p_ff;
    cudaGetSymbolAddress((void**)&p_xn, g_xn);
    cudaGetSymbolAddress((void**)&p_wqkv, g_wqkv);
    cudaGetSymbolAddress((void**)&p_qkv, g_qkv);
    cudaGetSymbolAddress((void**)&p_attn, g_attn);
    cudaGetSymbolAddress((void**)&p_h, g_h);
    cudaGetSymbolAddress((void**)&p_hn, g_hn);
    cudaGetSymbolAddress((void**)&p_ff, g_ff);

    // 1. LN1
    ln_kernel<<<BS, 256>>>(x, ln1_g, ln1_b, p_xn);

    // 2. rearrange QKV weights to [D, 3D]
    build_wqkv_kernel<<<(DD * D3 + 255) / 256, 256>>>(wq, wk, wv, p_wqkv);

    // 3. fused QKV GEMM: [4096,1024] @ [1024,3072]
    {
        dim3 grid(D3 / 128, BS / 128);
        sgemm_kernel<0><<<grid, 256>>>(p_xn, p_wqkv, nullptr, nullptr, p_qkv, BS, D3, DD);
    }

    // 4. flash attention
    {
        cudaFuncSetAttribute(attn_kernel, cudaFuncAttributeMaxDynamicSharedMemorySize,
                             ATT_SMEM_BYTES);
        dim3 grid(SS / 64, BB * HH);
        attn_kernel<<<grid, 256, ATT_SMEM_BYTES>>>(p_qkv, p_attn);
    }

    // 5. proj GEMM + bias + residual(x) -> h
    {
        dim3 grid(DD / 128, BS / 128);
        sgemm_kernel<0><<<grid, 256>>>(p_attn, wproj, bproj, x, p_h, BS, DD, DD);
    }

    // 6. LN2
    ln_kernel<<<BS, 256>>>(p_h, ln2_g, ln2_b, p_hn);

    // 7. FF1 + bias + relu
    {
        dim3 grid(DFF / 128, BS / 128);
        sgemm_kernel<1><<<grid, 256>>>(p_hn, w1, b1, nullptr, p_ff, BS, DFF, DD);
    }

    // 8. FF2 + bias + residual(h) -> out
    {
        dim3 grid(DD / 128, BS / 128);
        sgemm_kernel<0><<<grid, 256>>>(p_ff, w2, b2, p_h, out, BS, DD, DFF);
    }
}

// round 2
// speedup vs baseline: 2.6363x; 2.6363x over previous
#include <cuda_runtime.h>
#include <cuda_bf16.h>

// Problem constants
#define BB 2
#define SS 2048
#define DD 1024
#define HH 16
#define HSZ 64
#define BS (BB * SS)        // 4096 rows
#define D3 (3 * DD)         // 3072
#define DFF (4 * DD)        // 4096

// ---------------- scratch (static device memory; no allocations) ----------------
__device__ float g_xn[BS * DD];
__device__ float g_qkv[BS * D3];
__device__ float g_attn[BS * DD];
__device__ float g_h[BS * DD];
__device__ float g_hn[BS * DD];
__device__ float g_ff[BS * DFF];
__device__ float g_wqkvT[D3 * DD];    // [3072][1024]
__device__ float g_wprojT[DD * DD];   // [1024][1024]
__device__ float g_w1T[DFF * DD];     // [4096][1024]
__device__ float g_w2T[DD * DFF];     // [1024][4096]

// round-to-nearest tf32 (bit pattern is a valid fp32)
__device__ __forceinline__ float f2tf32(float x) {
    unsigned u;
    asm("cvt.rna.tf32.f32 %0, %1;" : "=r"(u) : "f"(x));
    return __uint_as_float(u);
}

// ---------------- LayerNorm (outputs tf32-rounded; consumers are tf32 GEMMs) ----
__global__ void ln_kernel(const float* __restrict__ in, const float* __restrict__ gamma,
                          const float* __restrict__ beta, float* __restrict__ out) {
    int row = blockIdx.x;
    int tid = threadIdx.x;
    float4 xv = ((const float4*)(in + (size_t)row * DD))[tid];

    __shared__ float red[256];
    red[tid] = xv.x + xv.y + xv.z + xv.w;
    __syncthreads();
    #pragma unroll
    for (int off = 128; off > 0; off >>= 1) {
        if (tid < off) red[tid] += red[tid + off];
        __syncthreads();
    }
    float mu = red[0] * (1.0f / DD);
    __syncthreads();

    float dx = xv.x - mu, dy = xv.y - mu, dz = xv.z - mu, dw = xv.w - mu;
    red[tid] = dx * dx + dy * dy + dz * dz + dw * dw;
    __syncthreads();
    #pragma unroll
    for (int off = 128; off > 0; off >>= 1) {
        if (tid < off) red[tid] += red[tid + off];
        __syncthreads();
    }
    float rstd = rsqrtf(red[0] * (1.0f / DD) + 1e-5f);

    float4 gv = ((const float4*)gamma)[tid];
    float4 bv = ((const float4*)beta)[tid];
    float4 ov;
    ov.x = f2tf32(dx * rstd * gv.x + bv.x);
    ov.y = f2tf32(dy * rstd * gv.y + bv.y);
    ov.z = f2tf32(dz * rstd * gv.z + bv.z);
    ov.w = f2tf32(dw * rstd * gv.w + bv.w);
    ((float4*)(out + (size_t)row * DD))[tid] = ov;
}

// ---------------- build wqkvT [3072][1024] (tf32-rounded) ----------------------
// wqkvT[part*1024 + h*64 + kk][d] = w_part[(h*1024 + d)*64 + kk]
__global__ void build_wqkvT_kernel(const float* __restrict__ wq, const float* __restrict__ wk,
                                   const float* __restrict__ wv, float* __restrict__ out) {
    __shared__ float sm[64][65];
    int dblk = blockIdx.x;     // 0..15
    int h = blockIdx.y;        // 0..15
    int part = blockIdx.z;     // 0..2
    const float* w = (part == 0) ? wq : (part == 1) ? wk : wv;
    int tid = threadIdx.x;     // 256
    int d0 = dblk * 64;

    int kk = tid & 63;
    int g4 = tid >> 6;
    #pragma unroll
    for (int i = 0; i < 16; i++) {
        int dl = g4 + i * 4;
        sm[dl][kk] = w[((size_t)(h * DD + d0 + dl)) * HSZ + kk];
    }
    __syncthreads();
    int dc = tid & 63;
    #pragma unroll
    for (int i = 0; i < 16; i++) {
        int kk2 = g4 + i * 4;
        out[(size_t)(part * DD + h * HSZ + kk2) * DD + d0 + dc] = f2tf32(sm[dc][kk2]);
    }
}

// ---------------- generic transpose: in[R][C] -> out[C][R] (tf32-rounded) ------
__global__ void transpose_kernel(const float* __restrict__ in, float* __restrict__ out,
                                 int R, int C) {
    __shared__ float t[32][33];
    int x = blockIdx.x * 32 + threadIdx.x;
    int y = blockIdx.y * 32 + threadIdx.y;
    #pragma unroll
    for (int i = 0; i < 32; i += 8)
        t[threadIdx.y + i][threadIdx.x] = in[(size_t)(y + i) * C + x];
    __syncthreads();
    x = blockIdx.y * 32 + threadIdx.x;
    y = blockIdx.x * 32 + threadIdx.y;
    #pragma unroll
    for (int i = 0; i < 32; i += 8)
        out[(size_t)(y + i) * R + x] = f2tf32(t[threadIdx.x][threadIdx.y + i]);
}

// ---------------- tf32 tensor-core GEMM --------------------------------------
// C[M,N] = A[M,K] @ Bt[N,K]^T (+bias)(+res)(relu,tf32-round). Tiles 128x128x32.
// 256 thr = 8 warps (2m x 4n), warp tile 64x32, mma m16n8k8 tf32.
#define GEMM_SMEM 65536

__device__ __forceinline__ void ldsm_x4(unsigned& r0, unsigned& r1, unsigned& r2, unsigned& r3,
                                        unsigned addr) {
    asm volatile("ldmatrix.sync.aligned.m8n8.x4.shared.b16 {%0,%1,%2,%3}, [%4];"
                 : "=r"(r0), "=r"(r1), "=r"(r2), "=r"(r3) : "r"(addr));
}

__device__ __forceinline__ void mma_tf32(float c[4], unsigned a0, unsigned a1, unsigned a2,
                                         unsigned a3, unsigned b0, unsigned b1) {
    asm volatile(
        "mma.sync.aligned.m16n8k8.row.col.f32.tf32.tf32.f32 "
        "{%0,%1,%2,%3}, {%4,%5,%6,%7}, {%8,%9}, {%0,%1,%2,%3};"
        : "+f"(c[0]), "+f"(c[1]), "+f"(c[2]), "+f"(c[3])
        : "r"(a0), "r"(a1), "r"(a2), "r"(a3), "r"(b0), "r"(b1));
}

#define CPA16(dst, src) \
    asm volatile("cp.async.cg.shared.global [%0], [%1], 16;" :: "r"(dst), "l"(src))

template <int RELU>
__global__ __launch_bounds__(256, 2)
void gemm_tc(const float* __restrict__ A, const float* __restrict__ Bt,
             const float* __restrict__ bias, const float* __restrict__ res,
             float* __restrict__ C, int M, int N, int K) {
    extern __shared__ unsigned smem_u[];
    unsigned sbase = (unsigned)__cvta_generic_to_shared(smem_u);

    int tid = threadIdx.x;
    int l = tid & 31;
    int wid = tid >> 5;
    int warp_m = wid >> 2;   // 0..1
    int warp_n = wid & 3;    // 0..3
    int bx = blockIdx.x * 128;
    int by = blockIdx.y * 128;

    float acc[4][4][4];
    #pragma unroll
    for (int i = 0; i < 4; i++)
        #pragma unroll
        for (int j = 0; j < 4; j++)
            #pragma unroll
            for (int k = 0; k < 4; k++) acc[i][j][k] = 0.0f;

    // gmem -> smem mapping: 4 rows per operand per thread, 16B each
    int lm = tid >> 3;                      // 0..31 (row within 32-row group)
    int kc = tid & 7;                       // 16B chunk within 32-float k row
    unsigned physw = (unsigned)((kc ^ (lm & 7)) * 4);  // swizzled word offset (const across i)
    const float* aptr = A + (size_t)(by + lm) * K + kc * 4;
    const float* bptr = Bt + (size_t)(bx + lm) * K + kc * 4;

    int NT = K / 32;

    // ldmatrix lane bases
    int rA = warp_m * 64 + (l & 7) + ((l >> 3) & 1) * 8;  // + mt*16
    int rB = warp_n * 32 + (l & 7) + ((l >> 4) & 1) * 8;  // + np*16
    int selA = (l >> 4) & 1;  // chunk select for A lanes
    int selB = (l >> 3) & 1;  // chunk select for B lanes
    int l7 = l & 7;

    auto issue = [&](int kt, int buf) {
        unsigned sA = sbase + buf * 32768u;
        unsigned sB = sA + 16384u;
        const float* ap = aptr + kt * 32;
        const float* bp = bptr + kt * 32;
        #pragma unroll
        for (int i = 0; i < 4; i++) {
            unsigned off = ((lm + 32 * i) * 32 + physw) * 4;
            CPA16(sA + off, ap + (size_t)(32 * i) * K);
            CPA16(sB + off, bp + (size_t)(32 * i) * K);
        }
        asm volatile("cp.async.commit_group;");
    };

    issue(0, 0);

    for (int kt = 0; kt < NT; kt++) {
        if (kt + 1 < NT) {
            issue(kt + 1, (kt + 1) & 1);
            asm volatile("cp.async.wait_group 1;" ::: "memory");
        } else {
            asm volatile("cp.async.wait_group 0;" ::: "memory");
        }
        __syncthreads();

        unsigned sA = sbase + (kt & 1) * 32768u;
        unsigned sB = sA + 16384u;

        #pragma unroll
        for (int ks = 0; ks < 4; ks++) {
            int physA = (2 * ks + selA) ^ l7;
            int physB = (2 * ks + selB) ^ l7;
            unsigned aBase = sA + (unsigned)(rA * 32 + physA * 4) * 4;
            unsigned bBase = sB + (unsigned)(rB * 32 + physB * 4) * 4;

            unsigned a[4][4], bf[2][4];
            #pragma unroll
            for (int mt = 0; mt < 4; mt++)
                ldsm_x4(a[mt][0], a[mt][1], a[mt][2], a[mt][3], aBase + mt * 2048u);
            #pragma unroll
            for (int np = 0; np < 2; np++)
                ldsm_x4(bf[np][0], bf[np][1], bf[np][2], bf[np][3], bBase + np * 2048u);

            #pragma unroll
            for (int mt = 0; mt < 4; mt++)
                #pragma unroll
                for (int nt = 0; nt < 4; nt++)
                    mma_tf32(acc[mt][nt], a[mt][0], a[mt][1], a[mt][2], a[mt][3],
                             bf[nt >> 1][(nt & 1) * 2], bf[nt >> 1][(nt & 1) * 2 + 1]);
        }
        __syncthreads();
    }

    // epilogue
    int g = l >> 2, tg = l & 3;
    #pragma unroll
    for (int mt = 0; mt < 4; mt++) {
        int r0 = by + warp_m * 64 + mt * 16 + g;
        #pragma unroll
        for (int nt = 0; nt < 4; nt++) {
            int col = bx + warp_n * 32 + nt * 8 + tg * 2;
            float2 v0 = make_float2(acc[mt][nt][0], acc[mt][nt][1]);
            float2 v1 = make_float2(acc[mt][nt][2], acc[mt][nt][3]);
            if (bias != nullptr) {
                float2 bv = *(const float2*)&bias[col];
                v0.x += bv.x; v0.y += bv.y; v1.x += bv.x; v1.y += bv.y;
            }
            if (res != nullptr) {
                float2 q0 = *(const float2*)&res[(size_t)r0 * N + col];
                float2 q1 = *(const float2*)&res[(size_t)(r0 + 8) * N + col];
                v0.x += q0.x; v0.y += q0.y; v1.x += q1.x; v1.y += q1.y;
            }
            if (RELU) {  // FF1: relu + tf32-round (feeds FF2 tf32 GEMM)
                v0.x = f2tf32(fmaxf(v0.x, 0.0f)); v0.y = f2tf32(fmaxf(v0.y, 0.0f));
                v1.x = f2tf32(fmaxf(v1.x, 0.0f)); v1.y = f2tf32(fmaxf(v1.y, 0.0f));
            }
            *(float2*)&C[(size_t)r0 * N + col] = v0;
            *(float2*)&C[(size_t)(r0 + 8) * N + col] = v1;
        }
    }
}

// ---------------- Flash attention (causal), fp32, 64x64 tiles ------------------
#define ATT_LD 68
#define ATT_SMEM_BYTES (4 * 64 * ATT_LD * 4)

__global__ void attn_kernel(const float* __restrict__ qkv, float* __restrict__ out) {
    extern __shared__ float sm[];
    float* QsT = sm;
    float* KsT = sm + 64 * ATT_LD;
    float* Vs  = sm + 2 * 64 * ATT_LD;
    float* PsT = sm + 3 * 64 * ATT_LD;

    int tid = threadIdx.x;
    int bh = blockIdx.y;
    int b = bh >> 4;
    int h = bh & 15;
    int q0 = blockIdx.x * 64;

    int R0 = (tid >> 4) << 2;
    int C0 = (tid & 15) << 2;

    {
        int r = tid >> 2, dg = tid & 3;
        const float* src = qkv + (size_t)(b * SS + q0 + r) * D3 + h * HSZ + dg * 16;
        #pragma unroll
        for (int i = 0; i < 4; i++) {
            float4 v = ((const float4*)src)[i];
            int d = dg * 16 + i * 4;
            QsT[(d + 0) * ATT_LD + r] = v.x;
            QsT[(d + 1) * ATT_LD + r] = v.y;
            QsT[(d + 2) * ATT_LD + r] = v.z;
            QsT[(d + 3) * ATT_LD + r] = v.w;
        }
    }

    float m[4], lsum[4], o[4][4];
    #pragma unroll
    for (int i = 0; i < 4; i++) {
        m[i] = -1e30f;
        lsum[i] = 0.0f;
        #pragma unroll
        for (int j = 0; j < 4; j++) o[i][j] = 0.0f;
    }
    const float scale = 0.125f;

    for (int k0 = 0; k0 <= q0; k0 += 64) {
        __syncthreads();
        {
            int r = tid >> 2, dg = tid & 3;
            const float* ksrc = qkv + (size_t)(b * SS + k0 + r) * D3 + DD + h * HSZ + dg * 16;
            #pragma unroll
            for (int i = 0; i < 4; i++) {
                float4 v = ((const float4*)ksrc)[i];
                int d = dg * 16 + i * 4;
                KsT[(d + 0) * ATT_LD + r] = v.x;
                KsT[(d + 1) * ATT_LD + r] = v.y;
                KsT[(d + 2) * ATT_LD + r] = v.z;
                KsT[(d + 3) * ATT_LD + r] = v.w;
            }
            const float* vsrc = qkv + (size_t)(b * SS + k0 + r) * D3 + 2 * DD + h * HSZ + dg * 16;
            #pragma unroll
            for (int i = 0; i < 4; i++)
                ((float4*)&Vs[r * ATT_LD + dg * 16])[i] = ((const float4*)vsrc)[i];
        }
        __syncthreads();

        float s4[4][4];
        #pragma unroll
        for (int i = 0; i < 4; i++)
            #pragma unroll
            for (int j = 0; j < 4; j++) s4[i][j] = 0.0f;

        #pragma unroll
        for (int d = 0; d < 64; d++) {
            float4 qa = *(const float4*)&QsT[d * ATT_LD + R0];
            float4 kb = *(const float4*)&KsT[d * ATT_LD + C0];
            float a[4] = {qa.x, qa.y, qa.z, qa.w};
            float bb[4] = {kb.x, kb.y, kb.z, kb.w};
            #pragma unroll
            for (int i = 0; i < 4; i++)
                #pragma unroll
                for (int j = 0; j < 4; j++)
                    s4[i][j] = fmaf(a[i], bb[j], s4[i][j]);
        }

        bool diag = (k0 == q0);
        #pragma unroll
        for (int i = 0; i < 4; i++)
            #pragma unroll
            for (int j = 0; j < 4; j++) {
                s4[i][j] *= scale;
                if (diag && (C0 + j > R0 + i)) s4[i][j] = -1e30f;
            }

        #pragma unroll
        for (int i = 0; i < 4; i++) {
            float tm = fmaxf(fmaxf(s4[i][0], s4[i][1]), fmaxf(s4[i][2], s4[i][3]));
            tm = fmaxf(tm, __shfl_xor_sync(0xffffffffu, tm, 1));
            tm = fmaxf(tm, __shfl_xor_sync(0xffffffffu, tm, 2));
            tm = fmaxf(tm, __shfl_xor_sync(0xffffffffu, tm, 4));
            tm = fmaxf(tm, __shfl_xor_sync(0xffffffffu, tm, 8));
            float mn = fmaxf(m[i], tm);
            float alpha = __expf(m[i] - mn);
            m[i] = mn;
            float ls = 0.0f;
            #pragma unroll
            for (int j = 0; j < 4; j++) {
                s4[i][j] = __expf(s4[i][j] - mn);
                ls += s4[i][j];
            }
            ls += __shfl_xor_sync(0xffffffffu, ls, 1);
            ls += __shfl_xor_sync(0xffffffffu, ls, 2);
            ls += __shfl_xor_sync(0xffffffffu, ls, 4);
            ls += __shfl_xor_sync(0xffffffffu, ls, 8);
            lsum[i] = lsum[i] * alpha + ls;
            #pragma unroll
            for (int j = 0; j < 4; j++) o[i][j] *= alpha;
        }

        #pragma unroll
        for (int j = 0; j < 4; j++) {
            float4 pv = make_float4(s4[0][j], s4[1][j], s4[2][j], s4[3][j]);
            *(float4*)&PsT[(C0 + j) * ATT_LD + R0] = pv;
        }
        __syncthreads();

        #pragma unroll
        for (int s = 0; s < 64; s++) {
            float4 pa = *(const float4*)&PsT[s * ATT_LD + R0];
            float4 vb = *(const float4*)&Vs[s * ATT_LD + C0];
            float p[4] = {pa.x, pa.y, pa.z, pa.w};
            float v[4] = {vb.x, vb.y, vb.z, vb.w};
            #pragma unroll
            for (int i = 0; i < 4; i++)
                #pragma unroll
                for (int j = 0; j < 4; j++)
                    o[i][j] = fmaf(p[i], v[j], o[i][j]);
        }
    }

    // epilogue: tf32-round (feeds proj tf32 GEMM)
    #pragma unroll
    for (int i = 0; i < 4; i++) {
        int row = q0 + R0 + i;
        float inv = 1.0f / lsum[i];
        float4 ov = make_float4(f2tf32(o[i][0] * inv), f2tf32(o[i][1] * inv),
                                f2tf32(o[i][2] * inv), f2tf32(o[i][3] * inv));
        *(float4*)&out[(size_t)(b * SS + row) * DD + h * HSZ + C0] = ov;
    }
}

// ---------------- launch ----------------
extern "C" void kernel_launch(void* const* d_in, const int* in_sizes, int n_in,
                              void* d_out, int out_size) {
    const float* x     = (const float*)d_in[0];
    const float* wq    = (const float*)d_in[1];
    const float* wk    = (const float*)d_in[2];
    const float* wv    = (const float*)d_in[3];
    const float* wproj = (const float*)d_in[4];
    const float* bproj = (const float*)d_in[5];
    const float* w1    = (const float*)d_in[6];
    const float* b1    = (const float*)d_in[7];
    const float* w2    = (const float*)d_in[8];
    const float* b2    = (const float*)d_in[9];
    const float* ln1_g = (const float*)d_in[10];
    const float* ln1_b = (const float*)d_in[11];
    const float* ln2_g = (const float*)d_in[12];
    const float* ln2_b = (const float*)d_in[13];
    float* out = (float*)d_out;

    float *p_xn, *p_qkv, *p_attn, *p_h, *p_hn, *p_ff;
    float *p_wqkvT, *p_wprojT, *p_w1T, *p_w2T;
    cudaGetSymbolAddress((void**)&p_xn, g_xn);
    cudaGetSymbolAddress((void**)&p_qkv, g_qkv);
    cudaGetSymbolAddress((void**)&p_attn, g_attn);
    cudaGetSymbolAddress((void**)&p_h, g_h);
    cudaGetSymbolAddress((void**)&p_hn, g_hn);
    cudaGetSymbolAddress((void**)&p_ff, g_ff);
    cudaGetSymbolAddress((void**)&p_wqkvT, g_wqkvT);
    cudaGetSymbolAddress((void**)&p_wprojT, g_wprojT);
    cudaGetSymbolAddress((void**)&p_w1T, g_w1T);
    cudaGetSymbolAddress((void**)&p_w2T, g_w2T);

    cudaFuncSetAttribute(gemm_tc<0>, cudaFuncAttributeMaxDynamicSharedMemorySize, GEMM_SMEM);
    cudaFuncSetAttribute(gemm_tc<1>, cudaFuncAttributeMaxDynamicSharedMemorySize, GEMM_SMEM);
    cudaFuncSetAttribute(attn_kernel, cudaFuncAttributeMaxDynamicSharedMemorySize,
                         ATT_SMEM_BYTES);

    // prep: LN1 + weight transposes (tf32-rounded)
    ln_kernel<<<BS, 256>>>(x, ln1_g, ln1_b, p_xn);
    build_wqkvT_kernel<<<dim3(16, 16, 3), 256>>>(wq, wk, wv, p_wqkvT);
    transpose_kernel<<<dim3(DD / 32, DD / 32), dim3(32, 8)>>>(wproj, p_wprojT, DD, DD);
    transpose_kernel<<<dim3(DFF / 32, DD / 32), dim3(32, 8)>>>(w1, p_w1T, DD, DFF);
    transpose_kernel<<<dim3(DD / 32, DFF / 32), dim3(32, 8)>>>(w2, p_w2T, DFF, DD);

    // QKV: [4096,1024] x [1024,3072]
    gemm_tc<0><<<dim3(D3 / 128, BS / 128), 256, GEMM_SMEM>>>(
        p_xn, p_wqkvT, nullptr, nullptr, p_qkv, BS, D3, DD);

    // attention
    attn_kernel<<<dim3(SS / 64, BB * HH), 256, ATT_SMEM_BYTES>>>(p_qkv, p_attn);

    // proj + bias + residual(x)
    gemm_tc<0><<<dim3(DD / 128, BS / 128), 256, GEMM_SMEM>>>(
        p_attn, p_wprojT, bproj, x, p_h, BS, DD, DD);

    // LN2
    ln_kernel<<<BS, 256>>>(p_h, ln2_g, ln2_b, p_hn);

    // FF1 + bias + relu (+tf32 round)
    gemm_tc<1><<<dim3(DFF / 128, BS / 128), 256, GEMM_SMEM>>>(
        p_hn, p_w1T, b1, nullptr, p_ff, BS, DFF, DD);

    // FF2 + bias + residual(h) -> out
    gemm_tc<0><<<dim3(DD / 128, BS / 128), 256, GEMM_SMEM>>>(
        p_ff, p_w2T, b2, p_h, out, BS, DD, DFF);
}

// round 3
// speedup vs baseline: 4.0410x; 1.5328x over previous
#include <cuda_runtime.h>
#include <cuda_bf16.h>

// Problem constants
#define BB 2
#define SS 2048
#define DD 1024
#define HH 16
#define HSZ 64
#define BS (BB * SS)        // 4096 rows
#define D3 (3 * DD)         // 3072
#define DFF (4 * DD)        // 4096

// ---------------- scratch (static device memory; no allocations) ----------------
__device__ float g_xn[BS * DD];
__device__ float g_qkv[BS * D3];
__device__ float g_attn[BS * DD];
__device__ float g_h[BS * DD];
__device__ float g_hn[BS * DD];
__device__ float g_ff[BS * DFF];
__device__ float g_wqkvT[D3 * DD];
__device__ float g_wprojT[DD * DD];
__device__ float g_w1T[DFF * DD];
__device__ float g_w2T[DD * DFF];

// round-to-nearest tf32 (bit pattern is a valid fp32)
__device__ __forceinline__ float f2tf32(float x) {
    unsigned u;
    asm("cvt.rna.tf32.f32 %0, %1;" : "=r"(u) : "f"(x));
    return __uint_as_float(u);
}

// ---------------- LayerNorm (outputs tf32-rounded) ----------------
__global__ void ln_kernel(const float* __restrict__ in, const float* __restrict__ gamma,
                          const float* __restrict__ beta, float* __restrict__ out) {
    int row = blockIdx.x;
    int tid = threadIdx.x;
    float4 xv = ((const float4*)(in + (size_t)row * DD))[tid];

    __shared__ float red[256];
    red[tid] = xv.x + xv.y + xv.z + xv.w;
    __syncthreads();
    #pragma unroll
    for (int off = 128; off > 0; off >>= 1) {
        if (tid < off) red[tid] += red[tid + off];
        __syncthreads();
    }
    float mu = red[0] * (1.0f / DD);
    __syncthreads();

    float dx = xv.x - mu, dy = xv.y - mu, dz = xv.z - mu, dw = xv.w - mu;
    red[tid] = dx * dx + dy * dy + dz * dz + dw * dw;
    __syncthreads();
    #pragma unroll
    for (int off = 128; off > 0; off >>= 1) {
        if (tid < off) red[tid] += red[tid + off];
        __syncthreads();
    }
    float rstd = rsqrtf(red[0] * (1.0f / DD) + 1e-5f);

    float4 gv = ((const float4*)gamma)[tid];
    float4 bv = ((const float4*)beta)[tid];
    float4 ov;
    ov.x = f2tf32(dx * rstd * gv.x + bv.x);
    ov.y = f2tf32(dy * rstd * gv.y + bv.y);
    ov.z = f2tf32(dz * rstd * gv.z + bv.z);
    ov.w = f2tf32(dw * rstd * gv.w + bv.w);
    ((float4*)(out + (size_t)row * DD))[tid] = ov;
}

// ---------------- build wqkvT [3072][1024] (tf32-rounded) ----------------------
__global__ void build_wqkvT_kernel(const float* __restrict__ wq, const float* __restrict__ wk,
                                   const float* __restrict__ wv, float* __restrict__ out) {
    __shared__ float sm[64][65];
    int dblk = blockIdx.x;
    int h = blockIdx.y;
    int part = blockIdx.z;
    const float* w = (part == 0) ? wq : (part == 1) ? wk : wv;
    int tid = threadIdx.x;
    int d0 = dblk * 64;

    int kk = tid & 63;
    int g4 = tid >> 6;
    #pragma unroll
    for (int i = 0; i < 16; i++) {
        int dl = g4 + i * 4;
        sm[dl][kk] = w[((size_t)(h * DD + d0 + dl)) * HSZ + kk];
    }
    __syncthreads();
    int dc = tid & 63;
    #pragma unroll
    for (int i = 0; i < 16; i++) {
        int kk2 = g4 + i * 4;
        out[(size_t)(part * DD + h * HSZ + kk2) * DD + d0 + dc] = f2tf32(sm[dc][kk2]);
    }
}

// ---------------- generic transpose: in[R][C] -> out[C][R] (tf32-rounded) ------
__global__ void transpose_kernel(const float* __restrict__ in, float* __restrict__ out,
                                 int R, int C) {
    __shared__ float t[32][33];
    int x = blockIdx.x * 32 + threadIdx.x;
    int y = blockIdx.y * 32 + threadIdx.y;
    #pragma unroll
    for (int i = 0; i < 32; i += 8)
        t[threadIdx.y + i][threadIdx.x] = in[(size_t)(y + i) * C + x];
    __syncthreads();
    x = blockIdx.y * 32 + threadIdx.x;
    y = blockIdx.x * 32 + threadIdx.y;
    #pragma unroll
    for (int i = 0; i < 32; i += 8)
        out[(size_t)(y + i) * R + x] = f2tf32(t[threadIdx.x][threadIdx.y + i]);
}

// ---------------- tf32 tensor-core GEMM helpers -------------------------------
#define GEMM_SMEM 65536

__device__ __forceinline__ void ldsm_x4(unsigned& r0, unsigned& r1, unsigned& r2, unsigned& r3,
                                        unsigned addr) {
    asm volatile("ldmatrix.sync.aligned.m8n8.x4.shared.b16 {%0,%1,%2,%3}, [%4];"
                 : "=r"(r0), "=r"(r1), "=r"(r2), "=r"(r3) : "r"(addr));
}

__device__ __forceinline__ void mma_tf32(float c[4], unsigned a0, unsigned a1, unsigned a2,
                                         unsigned a3, unsigned b0, unsigned b1) {
    asm volatile(
        "mma.sync.aligned.m16n8k8.row.col.f32.tf32.tf32.f32 "
        "{%0,%1,%2,%3}, {%4,%5,%6,%7}, {%8,%9}, {%0,%1,%2,%3};"
        : "+f"(c[0]), "+f"(c[1]), "+f"(c[2]), "+f"(c[3])
        : "r"(a0), "r"(a1), "r"(a2), "r"(a3), "r"(b0), "r"(b1));
}

#define CPA16(dst, src) \
    asm volatile("cp.async.cg.shared.global [%0], [%1], 16;" :: "r"(dst), "l"(src))

// MODE: 0 = plain, 1 = relu + tf32-round, 2 = tf32-round
template <int MODE>
__global__ __launch_bounds__(256, 2)
void gemm_tc(const float* __restrict__ A, const float* __restrict__ Bt,
             const float* __restrict__ bias, const float* __restrict__ res,
             float* __restrict__ C, int M, int N, int K) {
    extern __shared__ unsigned smem_u[];
    unsigned sbase = (unsigned)__cvta_generic_to_shared(smem_u);

    int tid = threadIdx.x;
    int l = tid & 31;
    int wid = tid >> 5;
    int warp_m = wid >> 2;
    int warp_n = wid & 3;
    int bx = blockIdx.x * 128;
    int by = blockIdx.y * 128;

    float acc[4][4][4];
    #pragma unroll
    for (int i = 0; i < 4; i++)
        #pragma unroll
        for (int j = 0; j < 4; j++)
            #pragma unroll
            for (int k = 0; k < 4; k++) acc[i][j][k] = 0.0f;

    int lm = tid >> 3;
    int kc = tid & 7;
    unsigned physw = (unsigned)((kc ^ (lm & 7)) * 4);
    const float* aptr = A + (size_t)(by + lm) * K + kc * 4;
    const float* bptr = Bt + (size_t)(bx + lm) * K + kc * 4;

    int NT = K / 32;

    int rA = warp_m * 64 + (l & 7) + ((l >> 3) & 1) * 8;
    int rB = warp_n * 32 + (l & 7) + ((l >> 4) & 1) * 8;
    int selA = (l >> 4) & 1;
    int selB = (l >> 3) & 1;
    int l7 = l & 7;

    auto issue = [&](int kt, int buf) {
        unsigned sA = sbase + buf * 32768u;
        unsigned sB = sA + 16384u;
        const float* ap = aptr + kt * 32;
        const float* bp = bptr + kt * 32;
        #pragma unroll
        for (int i = 0; i < 4; i++) {
            unsigned off = ((lm + 32 * i) * 32 + physw) * 4;
            CPA16(sA + off, ap + (size_t)(32 * i) * K);
            CPA16(sB + off, bp + (size_t)(32 * i) * K);
        }
        asm volatile("cp.async.commit_group;");
    };

    issue(0, 0);

    for (int kt = 0; kt < NT; kt++) {
        if (kt + 1 < NT) {
            issue(kt + 1, (kt + 1) & 1);
            asm volatile("cp.async.wait_group 1;" ::: "memory");
        } else {
            asm volatile("cp.async.wait_group 0;" ::: "memory");
        }
        __syncthreads();

        unsigned sA = sbase + (kt & 1) * 32768u;
        unsigned sB = sA + 16384u;

        #pragma unroll
        for (int ks = 0; ks < 4; ks++) {
            int physA = (2 * ks + selA) ^ l7;
            int physB = (2 * ks + selB) ^ l7;
            unsigned aBase = sA + (unsigned)(rA * 32 + physA * 4) * 4;
            unsigned bBase = sB + (unsigned)(rB * 32 + physB * 4) * 4;

            unsigned a[4][4], bf[2][4];
            #pragma unroll
            for (int mt = 0; mt < 4; mt++)
                ldsm_x4(a[mt][0], a[mt][1], a[mt][2], a[mt][3], aBase + mt * 2048u);
            #pragma unroll
            for (int np = 0; np < 2; np++)
                ldsm_x4(bf[np][0], bf[np][1], bf[np][2], bf[np][3], bBase + np * 2048u);

            #pragma unroll
            for (int mt = 0; mt < 4; mt++)
                #pragma unroll
                for (int nt = 0; nt < 4; nt++)
                    mma_tf32(acc[mt][nt], a[mt][0], a[mt][1], a[mt][2], a[mt][3],
                             bf[nt >> 1][(nt & 1) * 2], bf[nt >> 1][(nt & 1) * 2 + 1]);
        }
        __syncthreads();
    }

    int g = l >> 2, tg = l & 3;
    #pragma unroll
    for (int mt = 0; mt < 4; mt++) {
        int r0 = by + warp_m * 64 + mt * 16 + g;
        #pragma unroll
        for (int nt = 0; nt < 4; nt++) {
            int col = bx + warp_n * 32 + nt * 8 + tg * 2;
            float2 v0 = make_float2(acc[mt][nt][0], acc[mt][nt][1]);
            float2 v1 = make_float2(acc[mt][nt][2], acc[mt][nt][3]);
            if (bias != nullptr) {
                float2 bv = *(const float2*)&bias[col];
                v0.x += bv.x; v0.y += bv.y; v1.x += bv.x; v1.y += bv.y;
            }
            if (res != nullptr) {
                float2 q0 = *(const float2*)&res[(size_t)r0 * N + col];
                float2 q1 = *(const float2*)&res[(size_t)(r0 + 8) * N + col];
                v0.x += q0.x; v0.y += q0.y; v1.x += q1.x; v1.y += q1.y;
            }
            if (MODE == 1) {
                v0.x = f2tf32(fmaxf(v0.x, 0.0f)); v0.y = f2tf32(fmaxf(v0.y, 0.0f));
                v1.x = f2tf32(fmaxf(v1.x, 0.0f)); v1.y = f2tf32(fmaxf(v1.y, 0.0f));
            } else if (MODE == 2) {
                v0.x = f2tf32(v0.x); v0.y = f2tf32(v0.y);
                v1.x = f2tf32(v1.x); v1.y = f2tf32(v1.y);
            }
            *(float2*)&C[(size_t)r0 * N + col] = v0;
            *(float2*)&C[(size_t)(r0 + 8) * N + col] = v1;
        }
    }
}

// ---------------- tf32 tensor-core flash attention ----------------------------
// 128-query tile per CTA, 8 warps x 16 rows; 64-key tiles.
// smem (floats): Q[128][64] @0, K[64][64] @8192, VT[64][64] @12288, P[128][64] @16384
// all tiles: row stride 64 floats, 16B-chunk swizzle: phys = chunk ^ (row&7)
#define ATT_SMEM (24576 * 4)

__global__ __launch_bounds__(256, 2)
void attn_tc(const float* __restrict__ qkv, float* __restrict__ out) {
    extern __shared__ float sm[];
    unsigned ub = (unsigned)__cvta_generic_to_shared(sm);
    unsigned uQ = ub, uK = ub + 8192u * 4, uV = ub + 12288u * 4, uP = ub + 16384u * 4;

    int tid = threadIdx.x;
    int l = tid & 31, w = tid >> 5;
    int b = blockIdx.y >> 4, h = blockIdx.y & 15;
    int q0 = ((int)gridDim.x - 1 - (int)blockIdx.x) * 128;
    int nk = q0 / 64 + 2;

    const float* base = qkv + (size_t)b * SS * D3 + h * HSZ;

    // ---- prologue: Q + K(0) cp.async, V(0) regs ----
    int lr = tid >> 4, lc = tid & 15;
    unsigned lphys = (unsigned)(lc ^ (lr & 7));   // (row&7) constant across +16 passes
    {
        #pragma unroll
        for (int p = 0; p < 8; p++) {
            int row = lr + p * 16;
            CPA16(uQ + (unsigned)(row * 256) + lphys * 16,
                  base + (size_t)(q0 + row) * D3 + lc * 4);
        }
    }
    auto issueK = [&](int k0) {
        #pragma unroll
        for (int p = 0; p < 4; p++) {
            int row = lr + p * 16;
            CPA16(uK + (unsigned)(row * 256) + lphys * 16,
                  base + (size_t)(k0 + row) * D3 + DD + lc * 4);
        }
        asm volatile("cp.async.commit_group;");
    };
    int vs = tid & 63, vdg = tid >> 6;
    float vreg[16];
    auto loadV = [&](int k0) {
        const float* vp = base + (size_t)(k0 + vs) * D3 + 2 * DD + vdg * 16;
        #pragma unroll
        for (int ii = 0; ii < 4; ii++)
            *(float4*)&vreg[ii * 4] = ((const float4*)vp)[ii];
    };
    issueK(0);
    loadV(0);

    float m2[2] = {-1e30f, -1e30f};
    float l2[2] = {0.0f, 0.0f};
    float oacc[8][4];
    #pragma unroll
    for (int i = 0; i < 8; i++)
        #pragma unroll
        for (int j = 0; j < 4; j++) oacc[i][j] = 0.0f;

    int l7 = l & 7;
    int selA = (l >> 4) & 1, selB = (l >> 3) & 1;
    int rA = w * 16 + (l & 7) + ((l >> 3) & 1) * 8;
    int rB = (l & 7) + ((l >> 4) & 1) * 8;
    int rloc = w * 16 + (l >> 2);        // thread's row (i=0); i=1 -> +8

    for (int kt = 0; kt < nk; kt++) {
        int k0 = kt * 64;

        __syncthreads();   // prior PV reads of VT/P complete
        // store V transposed (tf32 already — rounded by QKV GEMM epilogue)
        #pragma unroll
        for (int ii = 0; ii < 4; ii++)
            #pragma unroll
            for (int j = 0; j < 4; j++) {
                int d = vdg * 16 + ii * 4 + j;
                int phys = (vs >> 2) ^ (d & 7);
                sm[12288 + d * 64 + phys * 4 + (vs & 3)] = vreg[ii * 4 + j];
            }
        asm volatile("cp.async.wait_group 0;" ::: "memory");
        __syncthreads();   // K + VT visible

        // ---- S = Q K^T ----
        float sacc[8][4];
        #pragma unroll
        for (int i = 0; i < 8; i++)
            #pragma unroll
            for (int j = 0; j < 4; j++) sacc[i][j] = 0.0f;

        #pragma unroll
        for (int ks = 0; ks < 8; ks++) {
            int pA = (2 * ks + selA) ^ l7;
            int pB = (2 * ks + selB) ^ l7;
            unsigned a0, a1, a2, a3;
            ldsm_x4(a0, a1, a2, a3, uQ + (unsigned)(rA * 256 + pA * 16));
            unsigned bf[4][4];
            #pragma unroll
            for (int np = 0; np < 4; np++)
                ldsm_x4(bf[np][0], bf[np][1], bf[np][2], bf[np][3],
                        uK + (unsigned)((rB + np * 16) * 256 + pB * 16));
            #pragma unroll
            for (int nt = 0; nt < 8; nt++)
                mma_tf32(sacc[nt], a0, a1, a2, a3,
                         bf[nt >> 1][(nt & 1) * 2], bf[nt >> 1][(nt & 1) * 2 + 1]);
        }

        // scale + causal mask
        #pragma unroll
        for (int nt = 0; nt < 8; nt++)
            #pragma unroll
            for (int e = 0; e < 4; e++) sacc[nt][e] *= 0.125f;
        if (kt >= nk - 2) {
            #pragma unroll
            for (int nt = 0; nt < 8; nt++)
                #pragma unroll
                for (int e = 0; e < 4; e++) {
                    int r = q0 + rloc + ((e >> 1) << 3);
                    int c = k0 + nt * 8 + 2 * (l & 3) + (e & 1);
                    if (c > r) sacc[nt][e] = -1e30f;
                }
        }

        // online softmax (2 rows per thread)
        #pragma unroll
        for (int i = 0; i < 2; i++) {
            float tm = -1e30f;
            #pragma unroll
            for (int nt = 0; nt < 8; nt++)
                tm = fmaxf(tm, fmaxf(sacc[nt][2 * i], sacc[nt][2 * i + 1]));
            tm = fmaxf(tm, __shfl_xor_sync(0xffffffffu, tm, 1));
            tm = fmaxf(tm, __shfl_xor_sync(0xffffffffu, tm, 2));
            float mn = fmaxf(m2[i], tm);
            float alpha = __expf(m2[i] - mn);
            m2[i] = mn;
            float ls = 0.0f;
            #pragma unroll
            for (int nt = 0; nt < 8; nt++) {
                float p0 = __expf(sacc[nt][2 * i] - mn);
                float p1 = __expf(sacc[nt][2 * i + 1] - mn);
                sacc[nt][2 * i] = p0;
                sacc[nt][2 * i + 1] = p1;
                ls += p0 + p1;
            }
            ls += __shfl_xor_sync(0xffffffffu, ls, 1);
            ls += __shfl_xor_sync(0xffffffffu, ls, 2);
            l2[i] = l2[i] * alpha + ls;
            #pragma unroll
            for (int nt = 0; nt < 8; nt++) {
                oacc[nt][2 * i] *= alpha;
                oacc[nt][2 * i + 1] *= alpha;
            }
        }

        // store P (tf32-rounded) to smem
        {
            int colb = 2 * (l & 3);
            #pragma unroll
            for (int nt = 0; nt < 8; nt++) {
                int phys = (2 * nt + ((l & 3) >> 1)) ^ ((l >> 2) & 7);
                float2 v0 = make_float2(f2tf32(sacc[nt][0]), f2tf32(sacc[nt][1]));
                float2 v1 = make_float2(f2tf32(sacc[nt][2]), f2tf32(sacc[nt][3]));
                *(float2*)&sm[16384 + rloc * 64 + phys * 4 + (colb & 3)] = v0;
                *(float2*)&sm[16384 + (rloc + 8) * 64 + phys * 4 + (colb & 3)] = v1;
            }
        }
        __syncthreads();   // P visible; all warps past S (K free to overwrite)

        // prefetch next tile
        if (kt + 1 < nk) {
            issueK(k0 + 64);
            loadV(k0 + 64);
        }

        // ---- O += P VT^T ----
        #pragma unroll
        for (int ks = 0; ks < 8; ks++) {
            int pA = (2 * ks + selA) ^ l7;
            int pB = (2 * ks + selB) ^ l7;
            unsigned a0, a1, a2, a3;
            ldsm_x4(a0, a1, a2, a3, uP + (unsigned)(rA * 256 + pA * 16));
            unsigned bf[4][4];
            #pragma unroll
            for (int np = 0; np < 4; np++)
                ldsm_x4(bf[np][0], bf[np][1], bf[np][2], bf[np][3],
                        uV + (unsigned)((rB + np * 16) * 256 + pB * 16));
            #pragma unroll
            for (int nt = 0; nt < 8; nt++)
                mma_tf32(oacc[nt], a0, a1, a2, a3,
                         bf[nt >> 1][(nt & 1) * 2], bf[nt >> 1][(nt & 1) * 2 + 1]);
        }
    }

    // epilogue: normalize, tf32-round (feeds proj GEMM), write [B,S,D]
    float inv0 = 1.0f / l2[0];
    float inv1 = 1.0f / l2[1];
    int r = q0 + rloc;
    int dcol = h * HSZ + 2 * (l & 3);
    #pragma unroll
    for (int nt = 0; nt < 8; nt++) {
        float2 v0 = make_float2(f2tf32(oacc[nt][0] * inv0), f2tf32(oacc[nt][1] * inv0));
        float2 v1 = make_float2(f2tf32(oacc[nt][2] * inv1), f2tf32(oacc[nt][3] * inv1));
        *(float2*)&out[(size_t)(b * SS + r) * DD + dcol + nt * 8] = v0;
        *(float2*)&out[(size_t)(b * SS + r + 8) * DD + dcol + nt * 8] = v1;
    }
}

// ---------------- launch ----------------
extern "C" void kernel_launch(void* const* d_in, const int* in_sizes, int n_in,
                              void* d_out, int out_size) {
    const float* x     = (const float*)d_in[0];
    const float* wq    = (const float*)d_in[1];
    const float* wk    = (const float*)d_in[2];
    const float* wv    = (const float*)d_in[3];
    const float* wproj = (const float*)d_in[4];
    const float* bproj = (const float*)d_in[5];
    const float* w1    = (const float*)d_in[6];
    const float* b1    = (const float*)d_in[7];
    const float* w2    = (const float*)d_in[8];
    const float* b2    = (const float*)d_in[9];
    const float* ln1_g = (const float*)d_in[10];
    const float* ln1_b = (const float*)d_in[11];
    const float* ln2_g = (const float*)d_in[12];
    const float* ln2_b = (const float*)d_in[13];
    float* out = (float*)d_out;

    float *p_xn, *p_qkv, *p_attn, *p_h, *p_hn, *p_ff;
    float *p_wqkvT, *p_wprojT, *p_w1T, *p_w2T;
    cudaGetSymbolAddress((void**)&p_xn, g_xn);
    cudaGetSymbolAddress((void**)&p_qkv, g_qkv);
    cudaGetSymbolAddress((void**)&p_attn, g_attn);
    cudaGetSymbolAddress((void**)&p_h, g_h);
    cudaGetSymbolAddress((void**)&p_hn, g_hn);
    cudaGetSymbolAddress((void**)&p_ff, g_ff);
    cudaGetSymbolAddress((void**)&p_wqkvT, g_wqkvT);
    cudaGetSymbolAddress((void**)&p_wprojT, g_wprojT);
    cudaGetSymbolAddress((void**)&p_w1T, g_w1T);
    cudaGetSymbolAddress((void**)&p_w2T, g_w2T);

    cudaFuncSetAttribute(gemm_tc<0>, cudaFuncAttributeMaxDynamicSharedMemorySize, GEMM_SMEM);
    cudaFuncSetAttribute(gemm_tc<1>, cudaFuncAttributeMaxDynamicSharedMemorySize, GEMM_SMEM);
    cudaFuncSetAttribute(gemm_tc<2>, cudaFuncAttributeMaxDynamicSharedMemorySize, GEMM_SMEM);
    cudaFuncSetAttribute(attn_tc, cudaFuncAttributeMaxDynamicSharedMemorySize, ATT_SMEM);

    // prep: LN1 + weight transposes (tf32-rounded)
    ln_kernel<<<BS, 256>>>(x, ln1_g, ln1_b, p_xn);
    build_wqkvT_kernel<<<dim3(16, 16, 3), 256>>>(wq, wk, wv, p_wqkvT);
    transpose_kernel<<<dim3(DD / 32, DD / 32), dim3(32, 8)>>>(wproj, p_wprojT, DD, DD);
    transpose_kernel<<<dim3(DFF / 32, DD / 32), dim3(32, 8)>>>(w1, p_w1T, DD, DFF);
    transpose_kernel<<<dim3(DD / 32, DFF / 32), dim3(32, 8)>>>(w2, p_w2T, DFF, DD);

    // QKV GEMM (epilogue tf32-rounds q/k/v for the tf32 attention)
    gemm_tc<2><<<dim3(D3 / 128, BS / 128), 256, GEMM_SMEM>>>(
        p_xn, p_wqkvT, nullptr, nullptr, p_qkv, BS, D3, DD);

    // tensor-core flash attention
    attn_tc<<<dim3(SS / 128, BB * HH), 256, ATT_SMEM>>>(p_qkv, p_attn);

    // proj + bias + residual(x)
    gemm_tc<0><<<dim3(DD / 128, BS / 128), 256, GEMM_SMEM>>>(
        p_attn, p_wprojT, bproj, x, p_h, BS, DD, DD);

    // LN2
    ln_kernel<<<BS, 256>>>(p_h, ln2_g, ln2_b, p_hn);

    // FF1 + bias + relu (+tf32 round)
    gemm_tc<1><<<dim3(DFF / 128, BS / 128), 256, GEMM_SMEM>>>(
        p_hn, p_w1T, b1, nullptr, p_ff, BS, DFF, DD);

    // FF2 + bias + residual(h) -> out
    gemm_tc<0><<<dim3(DD / 128, BS / 128), 256, GEMM_SMEM>>>(
        p_ff, p_w2T, b2, p_h, out, BS, DD, DFF);
}